// round 3
// baseline (speedup 1.0000x reference)
#include <cuda_runtime.h>

// ---------------- problem constants ----------------
#define LSEQ 4096
#define HDIM 512
#define PDIM 256
#define N2P  512          // 2*PDIM (re/im interleaved)
#define TCH  128          // scan chunk length
#define NCH  (LSEQ/TCH)   // 32 chunks
#define MAXB 8

// ---------------- scratch (no allocations allowed) ----------------
__device__ float  g_buf[(size_t)MAXB * LSEQ * N2P];   // Bu -> xs, in place (64 MB)
__device__ float2 g_carry[(size_t)MAXB * NCH * PDIM]; // chunk carries
__device__ float2 g_A[PDIM];                          // Lambda_bar
__device__ float2 g_AT[PDIM];                         // Lambda_bar^TCH
__device__ float2 g_coef[PDIM];                       // (Lambda_bar-1)/Lambda
__device__ float  g_W1[HDIM * N2P];                   // x -> Bu weight
__device__ float  g_W2[N2P * HDIM];                   // xs -> y weight

// ---------------- precompute scalars (1 block) ----------------
__global__ void k_precomp_scalar(const float* __restrict__ Lre,
                                 const float* __restrict__ Lim,
                                 const float* __restrict__ lstep) {
    int p = threadIdx.x;
    if (p >= PDIM) return;
    double lr = (double)Lre[p], li = (double)Lim[p];
    // match reference fp32 rounding points, fp64 transcendentals
    float stepf = (float)exp((double)lstep[p]);
    float arf = (float)(lr * (double)stepf);
    float aif = (float)(li * (double)stepf);
    float erf_ = (float)exp((double)arf);
    float cf  = (float)cos((double)aif);
    float sf  = (float)sin((double)aif);
    float2 a = make_float2(erf_ * cf, erf_ * sf);
    g_A[p] = a;
    // a^TCH via fp64 repeated squaring (TCH = 128 = 2^7)
    double ax = (double)a.x, ay = (double)a.y;
    #pragma unroll
    for (int i = 0; i < 7; i++) {
        double nx = ax * ax - ay * ay;
        double ny = 2.0 * ax * ay;
        ax = nx; ay = ny;
    }
    g_AT[p] = make_float2((float)ax, (float)ay);
    // coef = (a - 1)/lambda
    double nr = (double)a.x - 1.0, ni = (double)a.y;
    double den = lr * lr + li * li;
    g_coef[p] = make_float2((float)((nr * lr + ni * li) / den),
                            (float)((ni * lr - nr * li) / den));
}

// ---------------- build W1 (B_bar) and W2 (2*C / -2*C) ----------------
__global__ void k_precomp_w(const float* __restrict__ Bin,
                            const float* __restrict__ Cin) {
    int t = blockIdx.x * blockDim.x + threadIdx.x;   // over H*P
    if (t >= HDIM * PDIM) return;
    int h = t / PDIM, p = t % PDIM;
    float2 cf = g_coef[p];
    float br = Bin[(p * HDIM + h) * 2 + 0];
    float bi = Bin[(p * HDIM + h) * 2 + 1];
    g_W1[h * N2P + 2 * p]     = cf.x * br - cf.y * bi;
    g_W1[h * N2P + 2 * p + 1] = cf.x * bi + cf.y * br;
    float cr = Cin[(h * PDIM + p) * 2 + 0];
    float ci = Cin[(h * PDIM + p) * 2 + 1];
    g_W2[(2 * p)     * HDIM + h] =  2.0f * cr;
    g_W2[(2 * p + 1) * HDIM + h] = -2.0f * ci;
}

// ---------------- tiled SGEMM: C[M,N] = A[M,K] @ W[K,N] (+ D*Xs epilogue) ----
template<int EPI>
__global__ __launch_bounds__(256)
void k_sgemm(const float* __restrict__ A, const float* __restrict__ W,
             float* __restrict__ C, int M, int K, int N,
             const float* __restrict__ Dv, const float* __restrict__ Xs) {
    __shared__ float As[8][132];   // padded, transposed A tile
    __shared__ float Bs[8][128];
    int tid  = threadIdx.x;
    int brow = blockIdx.y * 128;
    int bcol = blockIdx.x * 128;

    int arow = tid >> 1;            // 0..127
    int acol = (tid & 1) << 2;      // 0 or 4
    int bkr  = tid >> 5;            // 0..7
    int bnc  = (tid & 31) << 2;     // 0..124
    int trow = (tid >> 4) << 3;     // 0..120 step 8
    int tcol = (tid & 15) << 3;     // 0..120 step 8

    float acc[8][8];
    #pragma unroll
    for (int i = 0; i < 8; i++)
        #pragma unroll
        for (int j = 0; j < 8; j++) acc[i][j] = 0.f;

    const float* Aptr = A + (size_t)(brow + arow) * K + acol;
    const float* Wptr = W + (size_t)bkr * N + bcol + bnc;

    for (int k0 = 0; k0 < K; k0 += 8) {
        float4 av = *(const float4*)(Aptr + k0);
        float4 bv = *(const float4*)(Wptr + (size_t)k0 * N);
        __syncthreads();
        As[acol + 0][arow] = av.x;
        As[acol + 1][arow] = av.y;
        As[acol + 2][arow] = av.z;
        As[acol + 3][arow] = av.w;
        *(float4*)&Bs[bkr][bnc] = bv;
        __syncthreads();
        #pragma unroll
        for (int kk = 0; kk < 8; kk++) {
            float4 a0 = *(const float4*)&As[kk][trow];
            float4 a1 = *(const float4*)&As[kk][trow + 4];
            float4 b0 = *(const float4*)&Bs[kk][tcol];
            float4 b1 = *(const float4*)&Bs[kk][tcol + 4];
            float ra[8] = {a0.x, a0.y, a0.z, a0.w, a1.x, a1.y, a1.z, a1.w};
            float rb[8] = {b0.x, b0.y, b0.z, b0.w, b1.x, b1.y, b1.z, b1.w};
            #pragma unroll
            for (int i = 0; i < 8; i++)
                #pragma unroll
                for (int j = 0; j < 8; j++)
                    acc[i][j] = fmaf(ra[i], rb[j], acc[i][j]);
        }
    }

    #pragma unroll
    for (int i = 0; i < 8; i++) {
        size_t row = (size_t)(brow + trow + i);
        #pragma unroll
        for (int j = 0; j < 8; j += 4) {
            size_t off = row * N + bcol + tcol + j;
            float4 v = make_float4(acc[i][j], acc[i][j + 1], acc[i][j + 2], acc[i][j + 3]);
            if (EPI) {
                float4 xv = *(const float4*)(Xs + off);
                v.x = fmaf(Dv[bcol + tcol + j + 0], xv.x, v.x);
                v.y = fmaf(Dv[bcol + tcol + j + 1], xv.y, v.y);
                v.z = fmaf(Dv[bcol + tcol + j + 2], xv.z, v.z);
                v.w = fmaf(Dv[bcol + tcol + j + 3], xv.w, v.w);
            }
            *(float4*)(C + off) = v;
        }
    }
}

// ---------------- chunk-local inclusive scan (in place) ----------------
__global__ void k_scan_chunks() {
    int p  = threadIdx.x;     // 0..255
    int ch = blockIdx.x;      // chunk
    int b  = blockIdx.y;      // batch
    float2 a = g_A[p];
    float2* buf = (float2*)g_buf;
    size_t base = ((size_t)b * LSEQ + (size_t)ch * TCH) * PDIM + p;
    float sx = 0.f, sy = 0.f;
    #pragma unroll 4
    for (int i = 0; i < TCH; i++) {
        float2 v = buf[base + (size_t)i * PDIM];
        float nx = fmaf(a.x, sx, fmaf(-a.y, sy, v.x));
        float ny = fmaf(a.x, sy, fmaf( a.y, sx, v.y));
        sx = nx; sy = ny;
        buf[base + (size_t)i * PDIM] = make_float2(sx, sy);
    }
    g_carry[((size_t)b * NCH + ch) * PDIM + p] = make_float2(sx, sy);
}

// ---------------- exclusive scan over chunk carries ----------------
__global__ void k_scan_carries() {
    int p = threadIdx.x;
    int b = blockIdx.x;
    float2 aT = g_AT[p];
    float sx = 0.f, sy = 0.f;
    for (int j = 0; j < NCH; j++) {
        size_t idx = ((size_t)b * NCH + j) * PDIM + p;
        float2 t = g_carry[idx];
        g_carry[idx] = make_float2(sx, sy);     // exclusive prefix
        float nx = fmaf(aT.x, sx, fmaf(-aT.y, sy, t.x));
        float ny = fmaf(aT.x, sy, fmaf( aT.y, sx, t.y));
        sx = nx; sy = ny;
    }
}

// ---------------- fixup: xs[i] += a^(i+1) * carry_prev ----------------
__global__ void k_fixup() {
    int p  = threadIdx.x;
    int ch = blockIdx.x;
    int b  = blockIdx.y;
    float2 c0 = g_carry[((size_t)b * NCH + ch) * PDIM + p];
    if (c0.x == 0.f && c0.y == 0.f) return;   // chunk 0 (and decayed-to-zero)
    float2 a = g_A[p];
    float2* buf = (float2*)g_buf;
    size_t base = ((size_t)b * LSEQ + (size_t)ch * TCH) * PDIM + p;
    float px = a.x, py = a.y;   // a^(i+1), starts at a^1
    #pragma unroll 4
    for (int i = 0; i < TCH; i++) {
        float2 v = buf[base + (size_t)i * PDIM];
        v.x = fmaf(px, c0.x, fmaf(-py, c0.y, v.x));
        v.y = fmaf(px, c0.y, fmaf( py, c0.x, v.y));
        buf[base + (size_t)i * PDIM] = v;
        float nx = px * a.x - py * a.y;
        float ny = px * a.y + py * a.x;
        px = nx; py = ny;
    }
}

// ---------------- launch ----------------
extern "C" void kernel_launch(void* const* d_in, const int* in_sizes, int n_in,
                              void* d_out, int out_size) {
    const float* x   = (const float*)d_in[0];
    const float* Lre = (const float*)d_in[1];
    const float* Lim = (const float*)d_in[2];
    const float* Bin = (const float*)d_in[3];
    const float* Cin = (const float*)d_in[4];
    const float* Dv  = (const float*)d_in[5];
    const float* ls  = (const float*)d_in[6];
    float* y = (float*)d_out;
    (void)n_in; (void)out_size;

    int Bsz = in_sizes[0] / (LSEQ * HDIM);
    if (Bsz > MAXB) Bsz = MAXB;
    int M = Bsz * LSEQ;

    float *bufp = nullptr, *w1p = nullptr, *w2p = nullptr;
    cudaGetSymbolAddress((void**)&bufp, g_buf);
    cudaGetSymbolAddress((void**)&w1p,  g_W1);
    cudaGetSymbolAddress((void**)&w2p,  g_W2);

    k_precomp_scalar<<<1, 256>>>(Lre, Lim, ls);
    k_precomp_w<<<(HDIM * PDIM + 255) / 256, 256>>>(Bin, Cin);

    // GEMM1: Bu = x @ W1   (M x 512 @ 512 x 512)
    dim3 g1(N2P / 128, M / 128);
    k_sgemm<0><<<g1, 256>>>(x, w1p, bufp, M, HDIM, N2P, nullptr, nullptr);

    // scan
    dim3 gs(NCH, Bsz);
    k_scan_chunks<<<gs, PDIM>>>();
    k_scan_carries<<<Bsz, PDIM>>>();
    k_fixup<<<gs, PDIM>>>();

    // GEMM2: y = xs @ W2 + D*x   (M x 512 @ 512 x 512)
    dim3 g2(HDIM / 128, M / 128);
    k_sgemm<1><<<g2, 256>>>(bufp, w2p, y, M, N2P, HDIM, Dv, x);
}

// round 6
// speedup vs baseline: 1.8628x; 1.8628x over previous
#include <cuda_runtime.h>
#include <cuda_bf16.h>
#include <cstdint>

// ---------------- problem constants ----------------
#define LSEQ 4096
#define HDIM 512
#define PDIM 256
#define N2P  512          // 2*PDIM (re/im interleaved)
#define KDIM 512
#define TCH  64           // scan chunk length
#define NCH  (LSEQ/TCH)   // 64 chunks
#define MAXB 8

// ---------------- scratch (no allocations allowed) ----------------
__device__ __align__(16) float  g_buf[(size_t)MAXB * LSEQ * N2P];        // Bu fp32 (scan in place)
__device__ __align__(16) __nv_bfloat16 g_xh[(size_t)MAXB * LSEQ * HDIM]; // x hi
__device__ __align__(16) __nv_bfloat16 g_xl[(size_t)MAXB * LSEQ * HDIM]; // x lo
__device__ __align__(16) __nv_bfloat16 g_sh[(size_t)MAXB * LSEQ * N2P];  // xs hi
__device__ __align__(16) __nv_bfloat16 g_sl[(size_t)MAXB * LSEQ * N2P];  // xs lo
__device__ float2 g_carry[(size_t)MAXB * NCH * PDIM];
__device__ float2 g_A[PDIM];
__device__ float2 g_AT[PDIM];          // Lambda_bar^TCH
__device__ float2 g_coef[PDIM];
__device__ __align__(16) __nv_bfloat16 g_W1h[(size_t)N2P * KDIM];   // [n=2p][k=h]
__device__ __align__(16) __nv_bfloat16 g_W1l[(size_t)N2P * KDIM];
__device__ __align__(16) __nv_bfloat16 g_W2h[(size_t)HDIM * KDIM];  // [n=h][k=2p]
__device__ __align__(16) __nv_bfloat16 g_W2l[(size_t)HDIM * KDIM];

// ---------------- small device helpers ----------------
__device__ __forceinline__ uint32_t smem_u32(const void* p) {
    uint32_t a;
    asm("{ .reg .u64 t; cvta.to.shared.u64 t, %1; cvt.u32.u64 %0, t; }"
        : "=r"(a) : "l"(p));
    return a;
}
__device__ __forceinline__ uint32_t lds32(uint32_t addr) {
    uint32_t v;
    asm volatile("ld.shared.b32 %0, [%1];" : "=r"(v) : "r"(addr));
    return v;
}
__device__ __forceinline__ void cpasync16(uint32_t dst, const void* src) {
    asm volatile("cp.async.cg.shared.global [%0], [%1], 16;"
                 :: "r"(dst), "l"(src) : "memory");
}
__device__ __forceinline__ void cp_commit() {
    asm volatile("cp.async.commit_group;" ::: "memory");
}
template<int N>
__device__ __forceinline__ void cp_wait() {
    asm volatile("cp.async.wait_group %0;" :: "n"(N) : "memory");
}
__device__ __forceinline__ void mma16816(float* d, const uint32_t* a, const uint32_t* b) {
    asm volatile(
        "mma.sync.aligned.m16n8k16.row.col.f32.bf16.bf16.f32 "
        "{%0,%1,%2,%3}, {%4,%5,%6,%7}, {%8,%9}, {%0,%1,%2,%3};"
        : "+f"(d[0]), "+f"(d[1]), "+f"(d[2]), "+f"(d[3])
        : "r"(a[0]), "r"(a[1]), "r"(a[2]), "r"(a[3]), "r"(b[0]), "r"(b[1]));
}
__device__ __forceinline__ void split2(float v, __nv_bfloat16& h, __nv_bfloat16& l) {
    h = __float2bfloat16(v);
    l = __float2bfloat16(v - __bfloat162float(h));
}
#define SWZ(o) ((o) ^ (((o) >> 3) & 0x70))

// ---------------- precompute scalars (1 block) ----------------
__global__ void k_precomp_scalar(const float* __restrict__ Lre,
                                 const float* __restrict__ Lim,
                                 const float* __restrict__ lstep) {
    int p = threadIdx.x;
    if (p >= PDIM) return;
    double lr = (double)Lre[p], li = (double)Lim[p];
    float stepf = (float)exp((double)lstep[p]);
    float arf = (float)(lr * (double)stepf);
    float aif = (float)(li * (double)stepf);
    float erf_ = (float)exp((double)arf);
    float cf  = (float)cos((double)aif);
    float sf  = (float)sin((double)aif);
    float2 a = make_float2(erf_ * cf, erf_ * sf);
    g_A[p] = a;
    double ax = (double)a.x, ay = (double)a.y;
    #pragma unroll
    for (int i = 0; i < 6; i++) {          // TCH = 64 = 2^6
        double nx = ax * ax - ay * ay;
        double ny = 2.0 * ax * ay;
        ax = nx; ay = ny;
    }
    g_AT[p] = make_float2((float)ax, (float)ay);
    double nr = (double)a.x - 1.0, ni = (double)a.y;
    double den = lr * lr + li * li;
    g_coef[p] = make_float2((float)((nr * lr + ni * li) / den),
                            (float)((ni * lr - nr * li) / den));
}

// ---------------- build bf16 hi/lo weights, N-major [n][k] ----------------
__global__ void k_precomp_w(const float* __restrict__ Bin,
                            const float* __restrict__ Cin) {
    int t = blockIdx.x * blockDim.x + threadIdx.x;   // over H*P
    if (t >= HDIM * PDIM) return;
    int h = t / PDIM, p = t % PDIM;
    float2 cf = g_coef[p];
    float br = Bin[(p * HDIM + h) * 2 + 0];
    float bi = Bin[(p * HDIM + h) * 2 + 1];
    float wre = cf.x * br - cf.y * bi;
    float wim = cf.x * bi + cf.y * br;
    split2(wre, g_W1h[(size_t)(2 * p) * KDIM + h], g_W1l[(size_t)(2 * p) * KDIM + h]);
    split2(wim, g_W1h[(size_t)(2 * p + 1) * KDIM + h], g_W1l[(size_t)(2 * p + 1) * KDIM + h]);
    float cr = Cin[(h * PDIM + p) * 2 + 0];
    float ci = Cin[(h * PDIM + p) * 2 + 1];
    split2( 2.0f * cr, g_W2h[(size_t)h * KDIM + 2 * p],     g_W2l[(size_t)h * KDIM + 2 * p]);
    split2(-2.0f * ci, g_W2h[(size_t)h * KDIM + 2 * p + 1], g_W2l[(size_t)h * KDIM + 2 * p + 1]);
}

// ---------------- x -> bf16 hi/lo ----------------
__global__ void k_cvt_x(const float* __restrict__ x, int n4) {
    int i = blockIdx.x * blockDim.x + threadIdx.x;
    if (i >= n4) return;
    float4 v = ((const float4*)x)[i];
    __nv_bfloat16 h0, h1, h2, h3, l0, l1, l2, l3;
    split2(v.x, h0, l0); split2(v.y, h1, l1);
    split2(v.z, h2, l2); split2(v.w, h3, l3);
    __nv_bfloat162 ph0 = __nv_bfloat162(h0, h1), ph1 = __nv_bfloat162(h2, h3);
    __nv_bfloat162 pl0 = __nv_bfloat162(l0, l1), pl1 = __nv_bfloat162(l2, l3);
    ((uint2*)g_xh)[i] = make_uint2(*(uint32_t*)&ph0, *(uint32_t*)&ph1);
    ((uint2*)g_xl)[i] = make_uint2(*(uint32_t*)&pl0, *(uint32_t*)&pl1);
}

// ---------------- mma.sync bf16 split GEMM: C[M,512] = A @ W^T (+ D*x) -------
// A: bf16 hi/lo [M][512] row-major; W: bf16 hi/lo [512][512] N-major [n][k].
// 128x128 CTA tile, K-chunk 64, 3-stage cp.async pipeline, SW128 smem.
// 256 threads = 8 warps, warp tile 32(M) x 64(N).
// Stage layout (64KB): Ah@0, Al@16K, Wh@32K, Wl@48K; 128 rows x 128B, swizzled.
#define GSTG 65536
#define GSMT (3 * GSTG)

template<int EPI>
__global__ void __launch_bounds__(256)
k_mmagemm(const __nv_bfloat16* __restrict__ Ahg, const __nv_bfloat16* __restrict__ Alg,
          const __nv_bfloat16* __restrict__ Whg, const __nv_bfloat16* __restrict__ Wlg,
          float* __restrict__ Cg, const float* __restrict__ Dv,
          const float* __restrict__ Xg) {
    extern __shared__ __align__(128) char smem[];
    uint32_t sb = smem_u32(smem);
    int tid = threadIdx.x, wid = tid >> 5, lid = tid & 31;
    int g = lid >> 2, t = lid & 3;
    int wm = (wid & 3) * 32, wn = (wid >> 2) * 64;
    size_t brow = (size_t)blockIdx.y * 128;
    size_t bcol = (size_t)blockIdx.x * 128;

    // gmem -> smem mapping: 2 threads per 128B row-chunk, 4 x 16B each
    int lrow = tid >> 1, lhalf = tid & 1;
    const char* srcAh = (const char*)(Ahg + (brow + lrow) * KDIM) + lhalf * 64;
    const char* srcAl = (const char*)(Alg + (brow + lrow) * KDIM) + lhalf * 64;
    const char* srcWh = (const char*)(Whg + (bcol + lrow) * KDIM) + lhalf * 64;
    const char* srcWl = (const char*)(Wlg + (bcol + lrow) * KDIM) + lhalf * 64;
    uint32_t dbase = (uint32_t)lrow * 128 + (uint32_t)lhalf * 64;

    float acc[2][8][4];
    #pragma unroll
    for (int mt = 0; mt < 2; mt++)
        #pragma unroll
        for (int nt = 0; nt < 8; nt++)
            #pragma unroll
            for (int j = 0; j < 4; j++) acc[mt][nt][j] = 0.f;

    auto load_stage = [&](int c, int s) {
        uint32_t st = sb + (uint32_t)s * GSTG;
        size_t ko = (size_t)c * 128;   // byte offset along K (64 bf16 per chunk)
        #pragma unroll
        for (int i = 0; i < 4; i++) {
            uint32_t d = SWZ(dbase + i * 16);
            cpasync16(st +         d, srcAh + ko + i * 16);
            cpasync16(st + 16384 + d, srcAl + ko + i * 16);
            cpasync16(st + 32768 + d, srcWh + ko + i * 16);
            cpasync16(st + 49152 + d, srcWl + ko + i * 16);
        }
        cp_commit();
    };

    auto compute_stage = [&](int s) {
        uint32_t st = sb + (uint32_t)s * GSTG;
        #pragma unroll
        for (int ks = 0; ks < 4; ks++) {
            uint32_t ah[2][4], al[2][4], bh[8][2], bl[8][2];
            #pragma unroll
            for (int mt = 0; mt < 2; mt++) {
                uint32_t r0 = (uint32_t)(wm + mt * 16 + g) * 128 + ks * 32 + t * 4;
                uint32_t r1 = r0 + 8 * 128;
                ah[mt][0] = lds32(st + SWZ(r0));
                ah[mt][1] = lds32(st + SWZ(r1));
                ah[mt][2] = lds32(st + SWZ(r0 + 16));
                ah[mt][3] = lds32(st + SWZ(r1 + 16));
                al[mt][0] = lds32(st + 16384 + SWZ(r0));
                al[mt][1] = lds32(st + 16384 + SWZ(r1));
                al[mt][2] = lds32(st + 16384 + SWZ(r0 + 16));
                al[mt][3] = lds32(st + 16384 + SWZ(r1 + 16));
            }
            #pragma unroll
            for (int nt = 0; nt < 8; nt++) {
                uint32_t r = (uint32_t)(wn + nt * 8 + g) * 128 + ks * 32 + t * 4;
                bh[nt][0] = lds32(st + 32768 + SWZ(r));
                bh[nt][1] = lds32(st + 32768 + SWZ(r + 16));
                bl[nt][0] = lds32(st + 49152 + SWZ(r));
                bl[nt][1] = lds32(st + 49152 + SWZ(r + 16));
            }
            #pragma unroll
            for (int mt = 0; mt < 2; mt++)
                #pragma unroll
                for (int nt = 0; nt < 8; nt++) {
                    mma16816(acc[mt][nt], ah[mt], bh[nt]);
                    mma16816(acc[mt][nt], ah[mt], bl[nt]);
                    mma16816(acc[mt][nt], al[mt], bh[nt]);
                }
        }
    };

    // 3-stage pipeline over 8 K-chunks
    load_stage(0, 0);
    load_stage(1, 1);
    cp_wait<1>();
    __syncthreads();
    #pragma unroll 1
    for (int c = 0; c < 8; c++) {
        if (c + 2 < 8) load_stage(c + 2, (c + 2) % 3);
        compute_stage(c % 3);
        if (c + 1 < 8) {
            cp_wait<1>();
            __syncthreads();
        }
    }

    // epilogue: accum -> gmem fp32 (+ D*x)
    #pragma unroll
    for (int mt = 0; mt < 2; mt++) {
        size_t r0 = brow + wm + mt * 16 + g;
        size_t r1 = r0 + 8;
        #pragma unroll
        for (int nt = 0; nt < 8; nt++) {
            size_t col = bcol + wn + nt * 8 + t * 2;
            float2 v0 = make_float2(acc[mt][nt][0], acc[mt][nt][1]);
            float2 v1 = make_float2(acc[mt][nt][2], acc[mt][nt][3]);
            if (EPI) {
                float2 d  = *(const float2*)(Dv + col);
                float2 x0 = *(const float2*)(Xg + r0 * 512 + col);
                float2 x1 = *(const float2*)(Xg + r1 * 512 + col);
                v0.x = fmaf(d.x, x0.x, v0.x); v0.y = fmaf(d.y, x0.y, v0.y);
                v1.x = fmaf(d.x, x1.x, v1.x); v1.y = fmaf(d.y, x1.y, v1.y);
            }
            *(float2*)(Cg + r0 * 512 + col) = v0;
            *(float2*)(Cg + r1 * 512 + col) = v1;
        }
    }
}

// ---------------- chunk-local inclusive scan (in place, fp32) ----------------
__global__ void k_scan_chunks() {
    int p  = threadIdx.x;
    int ch = blockIdx.x;
    int b  = blockIdx.y;
    float2 a = g_A[p];
    float2* buf = (float2*)g_buf;
    size_t base = ((size_t)b * LSEQ + (size_t)ch * TCH) * PDIM + p;
    float sx = 0.f, sy = 0.f;
    #pragma unroll 4
    for (int i = 0; i < TCH; i++) {
        float2 v = buf[base + (size_t)i * PDIM];
        float nx = fmaf(a.x, sx, fmaf(-a.y, sy, v.x));
        float ny = fmaf(a.x, sy, fmaf( a.y, sx, v.y));
        sx = nx; sy = ny;
        buf[base + (size_t)i * PDIM] = make_float2(sx, sy);
    }
    g_carry[((size_t)b * NCH + ch) * PDIM + p] = make_float2(sx, sy);
}

// ---------------- exclusive scan over chunk carries ----------------
__global__ void k_scan_carries() {
    int p = threadIdx.x;
    int b = blockIdx.x;
    float2 aT = g_AT[p];
    float sx = 0.f, sy = 0.f;
    for (int j = 0; j < NCH; j++) {
        size_t idx = ((size_t)b * NCH + j) * PDIM + p;
        float2 t = g_carry[idx];
        g_carry[idx] = make_float2(sx, sy);
        float nx = fmaf(aT.x, sx, fmaf(-aT.y, sy, t.x));
        float ny = fmaf(aT.x, sy, fmaf( aT.y, sx, t.y));
        sx = nx; sy = ny;
    }
}

// ---------------- fixup + convert to bf16 hi/lo ----------------
__global__ void k_fixup_cvt() {
    int p  = threadIdx.x;
    int ch = blockIdx.x;
    int b  = blockIdx.y;
    float2 c0 = g_carry[((size_t)b * NCH + ch) * PDIM + p];
    float2 a = g_A[p];
    float2* buf = (float2*)g_buf;
    size_t rbase = (size_t)b * LSEQ + (size_t)ch * TCH;
    float px = a.x, py = a.y;        // a^(i+1)
    #pragma unroll 4
    for (int i = 0; i < TCH; i++) {
        float2 v = buf[(rbase + i) * PDIM + p];
        v.x = fmaf(px, c0.x, fmaf(-py, c0.y, v.x));
        v.y = fmaf(px, c0.y, fmaf( py, c0.x, v.y));
        float nx = px * a.x - py * a.y;
        float ny = px * a.y + py * a.x;
        px = nx; py = ny;
        __nv_bfloat16 hr, lr, hi, li;
        split2(v.x, hr, lr);
        split2(v.y, hi, li);
        __nv_bfloat162 ph = __nv_bfloat162(hr, hi);
        __nv_bfloat162 pl = __nv_bfloat162(lr, li);
        size_t o = (rbase + i) * N2P + 2 * p;
        *(uint32_t*)(g_sh + o) = *(uint32_t*)&ph;
        *(uint32_t*)(g_sl + o) = *(uint32_t*)&pl;
    }
}

// ---------------- launch ----------------
extern "C" void kernel_launch(void* const* d_in, const int* in_sizes, int n_in,
                              void* d_out, int out_size) {
    const float* x   = (const float*)d_in[0];
    const float* Lre = (const float*)d_in[1];
    const float* Lim = (const float*)d_in[2];
    const float* Bin = (const float*)d_in[3];
    const float* Cin = (const float*)d_in[4];
    const float* Dv  = (const float*)d_in[5];
    const float* ls  = (const float*)d_in[6];
    float* y = (float*)d_out;
    (void)n_in; (void)out_size;

    int Bsz = in_sizes[0] / (LSEQ * HDIM);
    if (Bsz > MAXB) Bsz = MAXB;
    int M = Bsz * LSEQ;

    float *bufp = nullptr;
    __nv_bfloat16 *xh, *xl, *sh, *sl, *w1h, *w1l, *w2h, *w2l;
    cudaGetSymbolAddress((void**)&bufp, g_buf);
    cudaGetSymbolAddress((void**)&xh,  g_xh);
    cudaGetSymbolAddress((void**)&xl,  g_xl);
    cudaGetSymbolAddress((void**)&sh,  g_sh);
    cudaGetSymbolAddress((void**)&sl,  g_sl);
    cudaGetSymbolAddress((void**)&w1h, g_W1h);
    cudaGetSymbolAddress((void**)&w1l, g_W1l);
    cudaGetSymbolAddress((void**)&w2h, g_W2h);
    cudaGetSymbolAddress((void**)&w2l, g_W2l);

    cudaFuncSetAttribute(k_mmagemm<0>, cudaFuncAttributeMaxDynamicSharedMemorySize, GSMT);
    cudaFuncSetAttribute(k_mmagemm<1>, cudaFuncAttributeMaxDynamicSharedMemorySize, GSMT);

    k_precomp_scalar<<<1, 256>>>(Lre, Lim, ls);
    k_precomp_w<<<(HDIM * PDIM + 255) / 256, 256>>>(Bin, Cin);

    int n4 = M * HDIM / 4;
    k_cvt_x<<<(n4 + 255) / 256, 256>>>(x, n4);

    // GEMM1: Bu = x @ W1  -> g_buf (fp32)
    dim3 g1(N2P / 128, M / 128);
    k_mmagemm<0><<<g1, 256, GSMT>>>(xh, xl, w1h, w1l, bufp, nullptr, nullptr);

    // scan
    dim3 gs(NCH, Bsz);
    k_scan_chunks<<<gs, PDIM>>>();
    k_scan_carries<<<Bsz, PDIM>>>();
    k_fixup_cvt<<<gs, PDIM>>>();

    // GEMM2: y = xs @ W2 + D*x
    dim3 g2(HDIM / 128, M / 128);
    k_mmagemm<1><<<g2, 256, GSMT>>>(sh, sl, w2h, w2l, y, Dv, x);
}